// round 17
// baseline (speedup 1.0000x reference)
#include <cuda_runtime.h>
#include <cstdint>

#define BB 4
#define SEQ 2048
#define EMB 1024
#define NH 16
#define HD 64
#define MT (BB * SEQ)  // 8192 tokens

// Scratch (allocation-free rule: device globals)
__device__ float g_q[BB * NH * SEQ * HD];        // [b][h][s][d] fp32
// K packed tf32 tiles: [bh][jt][key 0..31][idx 0..31] x {comp0,comp1} uint32
__device__ uint32_t g_k2[BB * NH * 64 * 32 * 32 * 2];   // 33.5 MB
// V packed tf32 tiles: [bh][jt][d 0..63][kidx 0..15] x {comp} uint32
__device__ uint32_t g_v2[BB * NH * 64 * 64 * 16 * 2];   // 33.5 MB
__device__ float g_ao[MT * EMB];                 // attention out [m][e]

// ---------------------------------------------------------------------------
// tf32 helpers (baseline PTX, works at .target sm_100)
// ---------------------------------------------------------------------------
__device__ __forceinline__ uint32_t f2tf32(float x) {
  uint32_t r;
  asm("cvt.rna.tf32.f32 %0, %1;" : "=r"(r) : "f"(x));
  return r;
}

__device__ __forceinline__ float ex2(float x) {
  float r;
  asm("ex2.approx.f32 %0, %1;" : "=f"(r) : "f"(x));
  return r;
}

__device__ __forceinline__ void mma_tf32(float* c, const uint32_t* a,
                                         const uint32_t* b) {
  asm volatile(
      "mma.sync.aligned.m16n8k8.row.col.f32.tf32.tf32.f32 "
      "{%0,%1,%2,%3}, {%4,%5,%6,%7}, {%8,%9}, {%0,%1,%2,%3};"
      : "+f"(c[0]), "+f"(c[1]), "+f"(c[2]), "+f"(c[3])
      : "r"(a[0]), "r"(a[1]), "r"(a[2]), "r"(a[3]), "r"(b[0]), "r"(b[1]));
}

__device__ __forceinline__ void store_k2(int bh, int s, int d, float v) {
  const int jt = s >> 5, key = s & 31;
  const int idx = ((d >> 3) << 2) + (d & 3);
  const int comp = (d >> 2) & 1;
  g_k2[((((size_t)bh * 64 + jt) * 32 + key) * 32 + idx) * 2 + comp] = f2tf32(v);
}
__device__ __forceinline__ void store_v2(int bh, int s, int d, float v) {
  const int jt = s >> 5, key = s & 31;
  const int kidx = ((key >> 3) << 2) + (key & 3);
  const int comp = (key >> 2) & 1;
  g_v2[((((size_t)bh * 64 + jt) * 64 + d) * 16 + kidx) * 2 + comp] = f2tf32(v);
}

// ---------------------------------------------------------------------------
// PLAIN single-tf32 GEMM v2: smem holds (k, k+4) uint2 PAIRS — each mma
// fragment fetch is one LDS.64 (frag LDS instr 48 -> 24 per chunk/thread;
// LSU ops 56 -> 36). Row stride 12 uint2 (24 words): load phases hit banks
// {0-7,24-31,16-23,8-15} — conflict-free; stores accept a 2-way on half
// phases (4 instr/chunk, negligible). Warp tile 64x32, double-buffered,
// ONE sync per BK=16 chunk, __launch_bounds__(256,2).
// MODE 0: A=query; epilogue scatters Q (fp32) and K/V (packed tf32 tiles).
// MODE 1: A=g_ao, write out.
// ---------------------------------------------------------------------------
#define SU2 12                        // uint2 row stride (data in idx 0..7)
#define TILEU2 (128 * SU2)            // one operand tile in uint2
#define GEMM_SMEM_BYTES (2 * 2 * TILEU2 * 8)  // 2 bufs x {A,B} = 49152 B

template <int MODE>
__global__ __launch_bounds__(256, 2) void gemm_mma_kernel(
    const float* __restrict__ A, const float* __restrict__ B,
    const float* __restrict__ bias, float* __restrict__ out) {
  extern __shared__ uint2 gsm[];

  const int tid = threadIdx.x;
  const int lane = tid & 31;
  const int wid = tid >> 5;
  const int warp_m = wid & 1;        // 2 warps over M
  const int warp_n = wid >> 1;       // 4 warps over N
  const int m0 = blockIdx.y * 128;
  const int n0 = blockIdx.x * 128;

  const float* Asrc = (MODE == 0) ? A : g_ao;

  // loader mapping: 4 threads per row; thread q covers k-pair block
  //   q -> kc = q>>1, j = q&1; k offset = kc*8 + j*2; uint2 idx = kc*4 + j*2
  const int ldr = tid >> 2;          // rows 0..63 (+64 for second half)
  const int q = tid & 3;
  const int kof = (q >> 1) * 8 + (q & 1) * 2;
  const int sidx = (q >> 1) * 4 + (q & 1) * 2;

  const float* Ap0 = Asrc + (size_t)(m0 + ldr) * EMB + kof;
  const float* Ap1 = Asrc + (size_t)(m0 + 64 + ldr) * EMB + kof;
  const float* Bp0 = B + (size_t)(n0 + ldr) * EMB + kof;
  const float* Bp1 = B + (size_t)(n0 + 64 + ldr) * EMB + kof;

  float acc[4][4][4] = {};  // [mt][nt][reg]

  const int s0 = ldr * SU2 + sidx;
  const int s1 = (ldr + 64) * SU2 + sidx;

  // prefetch chunk 0 (pairs: lo = k..k+1, hi = k+4..k+5)
  float2 a0l = *(const float2*)(Ap0),     a0h = *(const float2*)(Ap0 + 4);
  float2 a1l = *(const float2*)(Ap1),     a1h = *(const float2*)(Ap1 + 4);
  float2 b0l = *(const float2*)(Bp0),     b0h = *(const float2*)(Bp0 + 4);
  float2 b1l = *(const float2*)(Bp1),     b1h = *(const float2*)(Bp1 + 4);

  // pack pair-store: uint4 = {(k),(k+4),(k+1),(k+5)} = 2 uint2 pairs
#define PAIR_STORE(T, idx, vl, vh)                                  \
  do {                                                              \
    uint4 u;                                                        \
    u.x = f2tf32((vl).x); u.y = f2tf32((vh).x);                     \
    u.z = f2tf32((vl).y); u.w = f2tf32((vh).y);                     \
    *(uint4*)&(T)[idx] = u;                                         \
  } while (0)

  // prologue: chunk 0 -> buffer 0
  {
    uint2* At = gsm;
    uint2* Bt = gsm + TILEU2;
    PAIR_STORE(At, s0, a0l, a0h);
    PAIR_STORE(At, s1, a1l, a1h);
    PAIR_STORE(Bt, s0, b0l, b0h);
    PAIR_STORE(Bt, s1, b1l, b1h);
  }

  for (int c = 0; c < EMB / 16; ++c) {
    __syncthreads();  // stores of chunk c done; computes of chunk c-1 done

    const bool more = (c + 1 < EMB / 16);
    if (more) {
      const int off = (c + 1) * 16;
      a0l = *(const float2*)(Ap0 + off); a0h = *(const float2*)(Ap0 + off + 4);
      a1l = *(const float2*)(Ap1 + off); a1h = *(const float2*)(Ap1 + off + 4);
      b0l = *(const float2*)(Bp0 + off); b0h = *(const float2*)(Bp0 + off + 4);
      b1l = *(const float2*)(Bp1 + off); b1h = *(const float2*)(Bp1 + off + 4);
    }

    // compute chunk c from buffer c&1
    {
      const uint2* cb = gsm + (c & 1) * (2 * TILEU2);
      const uint2* s_a = cb;
      const uint2* s_b = cb + TILEU2;
#pragma unroll
      for (int kc = 0; kc < 2; ++kc) {
        const int kb2 = kc * 4 + (lane & 3);
        uint32_t ah[4][4];
#pragma unroll
        for (int mt = 0; mt < 4; ++mt) {
          const int r = warp_m * 64 + mt * 16 + (lane >> 2);
          const uint2 x0 = s_a[r * SU2 + kb2];
          const uint2 x1 = s_a[(r + 8) * SU2 + kb2];
          ah[mt][0] = x0.x; ah[mt][1] = x1.x;
          ah[mt][2] = x0.y; ah[mt][3] = x1.y;
        }
        uint32_t bh[4][2];
#pragma unroll
        for (int nt = 0; nt < 4; ++nt) {
          const int n = warp_n * 32 + nt * 8 + (lane >> 2);
          const uint2 y = s_b[n * SU2 + kb2];
          bh[nt][0] = y.x; bh[nt][1] = y.y;
        }
#pragma unroll
        for (int mt = 0; mt < 4; ++mt)
#pragma unroll
          for (int nt = 0; nt < 4; ++nt)
            mma_tf32(acc[mt][nt], ah[mt], bh[nt]);
      }
    }

    // store chunk c+1 into the other buffer (its readers are done)
    if (more) {
      uint2* nb = gsm + ((c + 1) & 1) * (2 * TILEU2);
      uint2* At = nb;
      uint2* Bt = nb + TILEU2;
      PAIR_STORE(At, s0, a0l, a0h);
      PAIR_STORE(At, s1, a1l, a1h);
      PAIR_STORE(Bt, s0, b0l, b0h);
      PAIR_STORE(Bt, s1, b1l, b1h);
    }
  }

#pragma unroll
  for (int mt = 0; mt < 4; ++mt) {
#pragma unroll
    for (int nt = 0; nt < 4; ++nt) {
      const int r = m0 + warp_m * 64 + mt * 16 + (lane >> 2);
      const int n = n0 + warp_n * 32 + nt * 8 + (lane & 3) * 2;
      const float b0 = bias[n], b1 = bias[n + 1];
      float2 v0 = {acc[mt][nt][0] + b0, acc[mt][nt][1] + b1};
      float2 v1 = {acc[mt][nt][2] + b0, acc[mt][nt][3] + b1};
      if (MODE == 0) {
        const int which = n >> 10;
        const int rem = n & 1023;
        const int h = rem >> 6;
        const int d = rem & 63;
        const int b_ = r >> 11, s_ = r & 2047;
        const int bh = (b_ << 4) + h;
        if (which == 0) {
          float* base = g_q + ((size_t)bh * SEQ) * HD + d;
          *(float2*)(base + (size_t)s_ * HD) = v0;
          *(float2*)(base + (size_t)(s_ + 8) * HD) = v1;
        } else if (which == 1) {
          store_k2(bh, s_, d, v0.x);     store_k2(bh, s_, d + 1, v0.y);
          store_k2(bh, s_ + 8, d, v1.x); store_k2(bh, s_ + 8, d + 1, v1.y);
        } else {
          store_v2(bh, s_, d, v0.x);     store_v2(bh, s_, d + 1, v0.y);
          store_v2(bh, s_ + 8, d, v1.x); store_v2(bh, s_ + 8, d + 1, v1.y);
        }
      } else {
        *(float2*)(out + (size_t)r * EMB + n) = v0;
        *(float2*)(out + (size_t)(r + 8) * EMB + n) = v1;
      }
    }
  }
}

// ---------------------------------------------------------------------------
// Flash attention v6 (UNCHANGED from R16 — measured ~560us):
// K/V arrive PRE-PACKED tf32 from qkv epilogue; staging = 4 LDG.128 +
// 4 STS.128 per thread/tile. Fixed-bias softmax, private l. Plain tf32 mma,
// CTA = 128 q-rows, 256 threads / 8 warps, KV tiles 32, double-buffered,
// register prefetch, ONE sync per tile.
// ---------------------------------------------------------------------------
#define AT_K2_OFF 0
#define AT_V2_OFF (2 * 9216)
#define AT_P2_OFF (2 * 9216 + 2 * 10240)
#define ATTN_SMEM_BYTES (AT_P2_OFF + 128 * 20 * 8)  // 59392

__global__ __launch_bounds__(256, 2) void flash_mma_kernel() {
  extern __shared__ char asm_raw[];
  float (*Qs)[68] = reinterpret_cast<float(*)[68]>(asm_raw);
  uint2 (*P2)[20] = reinterpret_cast<uint2(*)[20]>(asm_raw + AT_P2_OFF);

  const int tid = threadIdx.x;
  const int lane = tid & 31;
  const int w = tid >> 5;
  const int grp = lane >> 2;     // 0..7
  const int qp = lane & 3;       // 0..3
  const int bh = blockIdx.x;     // 0..63
  const int q0 = blockIdx.y * 128;
  const int b = bh >> 4, h = bh & 15;
  const int qrow = w * 16 + grp;
  const float SCALE2 = 0.03125f * 1.44269504089f;  // log2e / sqrt(1024)
  const float BIAS = 4.0f;                          // fixed softmax shift

  const float* Qg = g_q + (size_t)(bh * SEQ + q0) * HD;
  const uint4* K2g = (const uint4*)g_k2 + (size_t)bh * 64 * 512;
  const uint4* V2g = (const uint4*)g_v2 + (size_t)bh * 64 * 512;

#pragma unroll
  for (int it = 0; it < 8; ++it) {
    const int slot = it * 256 + tid;
    const int r = slot >> 4;
    const int c = (slot & 15) * 4;
    *(float4*)&Qs[r][c] = *(const float4*)(Qg + r * HD + c);
  }
  __syncthreads();

  uint32_t qf[8][4];
#pragma unroll
  for (int ks = 0; ks < 8; ++ks) {
    qf[ks][0] = f2tf32(Qs[qrow][ks * 8 + qp] * SCALE2);
    qf[ks][1] = f2tf32(Qs[qrow + 8][ks * 8 + qp] * SCALE2);
    qf[ks][2] = f2tf32(Qs[qrow][ks * 8 + qp + 4] * SCALE2);
    qf[ks][3] = f2tf32(Qs[qrow + 8][ks * 8 + qp + 4] * SCALE2);
  }

  const int ia = tid, ib = tid + 256;
  const int kOffA = (ia >> 4) * 288 + (ia & 15) * 16;   // byte in K2 tile
  const int kOffB = (ib >> 4) * 288 + (ib & 15) * 16;
  const int vOffA = (ia >> 3) * 160 + (ia & 7) * 16;    // byte in V2 tile
  const int vOffB = (ib >> 3) * 160 + (ib & 7) * 16;

  uint4 kpa = K2g[ia], kpb = K2g[ib];
  uint4 vpa = V2g[ia], vpb = V2g[ib];

  __syncthreads();  // Q fragments extracted -> safe to overwrite Qs union

  float o[8][4] = {};
  float l0v = 0.f, l1v = 0.f;   // private partial sums (reduced at end)

  {
    char* kb0 = asm_raw + AT_K2_OFF;
    char* vb0 = asm_raw + AT_V2_OFF;
    *(uint4*)(kb0 + kOffA) = kpa;
    *(uint4*)(kb0 + kOffB) = kpb;
    *(uint4*)(vb0 + vOffA) = vpa;
    *(uint4*)(vb0 + vOffB) = vpb;
  }

  for (int jt = 0; jt < SEQ / 32; ++jt) {
    __syncthreads();  // tile jt stored; tile jt-1 readers done

    const bool more = (jt + 1 < SEQ / 32);
    if (more) {
      const size_t tb = (size_t)(jt + 1) * 512;
      kpa = K2g[tb + ia]; kpb = K2g[tb + ib];
      vpa = V2g[tb + ia]; vpb = V2g[tb + ib];
    }

    const int cbuf = jt & 1;
    uint2 (*K2)[36] = reinterpret_cast<uint2(*)[36]>(asm_raw + AT_K2_OFF + cbuf * 9216);
    uint2 (*V2)[20] = reinterpret_cast<uint2(*)[20]>(asm_raw + AT_V2_OFF + cbuf * 10240);

    float s[4][4] = {};
#pragma unroll
    for (int ks = 0; ks < 8; ++ks) {
#pragma unroll
      for (int nt = 0; nt < 4; ++nt) {
        const uint2 bv = K2[nt * 8 + grp][ks * 4 + qp];
        uint32_t b2[2] = {bv.x, bv.y};
        mma_tf32(s[nt], qf[ks], b2);
      }
    }

    float p[4][4];
#pragma unroll
    for (int nt = 0; nt < 4; ++nt) {
      p[nt][0] = ex2(s[nt][0] - BIAS);
      p[nt][1] = ex2(s[nt][1] - BIAS);
      p[nt][2] = ex2(s[nt][2] - BIAS);
      p[nt][3] = ex2(s[nt][3] - BIAS);
      l0v += p[nt][0] + p[nt][1];
      l1v += p[nt][2] + p[nt][3];
    }

#pragma unroll
    for (int nt = 0; nt < 4; ++nt) {
#pragma unroll
      for (int j = 0; j < 2; ++j) {
        const int col = nt * 8 + qp * 2 + j;
        const int kst = col >> 3;
        const int idx = kst * 4 + (col & 3);
        const int comp = (col >> 2) & 1;
        ((uint32_t*)&P2[qrow][idx])[comp] = f2tf32(p[nt][j]);
        ((uint32_t*)&P2[qrow + 8][idx])[comp] = f2tf32(p[nt][2 + j]);
      }
    }
    __syncwarp();

#pragma unroll
    for (int kst = 0; kst < 4; ++kst) {
      const uint2 pa0 = P2[qrow][kst * 4 + qp];
      const uint2 pa1 = P2[qrow + 8][kst * 4 + qp];
      uint32_t a2[4] = {pa0.x, pa1.x, pa0.y, pa1.y};
#pragma unroll
      for (int dt = 0; dt < 8; ++dt) {
        const uint2 vb = V2[dt * 8 + grp][kst * 4 + qp];
        uint32_t b2[2] = {vb.x, vb.y};
        mma_tf32(o[dt], a2, b2);
      }
    }

    if (more) {
      char* kbn = asm_raw + AT_K2_OFF + (cbuf ^ 1) * 9216;
      char* vbn = asm_raw + AT_V2_OFF + (cbuf ^ 1) * 10240;
      *(uint4*)(kbn + kOffA) = kpa;
      *(uint4*)(kbn + kOffB) = kpb;
      *(uint4*)(vbn + vOffA) = vpa;
      *(uint4*)(vbn + vOffB) = vpb;
    }
  }

  l0v += __shfl_xor_sync(0xffffffffu, l0v, 1);
  l0v += __shfl_xor_sync(0xffffffffu, l0v, 2);
  l1v += __shfl_xor_sync(0xffffffffu, l1v, 1);
  l1v += __shfl_xor_sync(0xffffffffu, l1v, 2);

  const float il0 = 1.f / l0v;
  const float il1 = 1.f / l1v;
  float* aob = g_ao + ((size_t)(b * SEQ + q0)) * EMB + h * HD;
#pragma unroll
  for (int dt = 0; dt < 8; ++dt) {
    const int d0 = dt * 8 + qp * 2;
    float2 v0 = {o[dt][0] * il0, o[dt][1] * il0};
    float2 v1 = {o[dt][2] * il1, o[dt][3] * il1};
    *(float2*)(aob + (size_t)qrow * EMB + d0) = v0;
    *(float2*)(aob + (size_t)(qrow + 8) * EMB + d0) = v1;
  }
}

// ---------------------------------------------------------------------------
extern "C" void kernel_launch(void* const* d_in, const int* in_sizes, int n_in,
                              void* d_out, int out_size) {
  (void)in_sizes; (void)n_in; (void)out_size;
  const float* query = (const float*)d_in[0];
  // d_in[1]=key, d_in[2]=value: ignored by the reference module
  const float* Wqkv = (const float*)d_in[3];
  const float* bqkv = (const float*)d_in[4];
  const float* Wout = (const float*)d_in[5];
  const float* bout = (const float*)d_in[6];
  float* out = (float*)d_out;

  cudaFuncSetAttribute(gemm_mma_kernel<0>,
                       cudaFuncAttributeMaxDynamicSharedMemorySize,
                       GEMM_SMEM_BYTES);
  cudaFuncSetAttribute(gemm_mma_kernel<1>,
                       cudaFuncAttributeMaxDynamicSharedMemorySize,
                       GEMM_SMEM_BYTES);
  cudaFuncSetAttribute(flash_mma_kernel,
                       cudaFuncAttributeMaxDynamicSharedMemorySize,
                       ATTN_SMEM_BYTES);

  dim3 g1(24, 64);   // 3072/128 x 8192/128
  gemm_mma_kernel<0><<<g1, 256, GEMM_SMEM_BYTES>>>(query, Wqkv, bqkv, nullptr);

  dim3 g2(64, 16);   // (b*h) x (S/128)
  flash_mma_kernel<<<g2, 256, ATTN_SMEM_BYTES>>>();

  dim3 g3(8, 64);    // 1024/128 x 8192/128
  gemm_mma_kernel<1><<<g3, 256, GEMM_SMEM_BYTES>>>(nullptr, Wout, bout, out);
}